// round 9
// baseline (speedup 1.0000x reference)
#include <cuda_runtime.h>
#include <cuda_bf16.h>
#include <math.h>
#include <stdint.h>

// Problem constants
#define Hdim 1024
#define Idim 4096
#define NE   8
#define NT   2048
#define NSLOT 6144
#define SHOFF 4096

// ---------------- scratch ------------------------------------------------------
__device__ float g_hact[(size_t)NSLOT * Idim];
__device__ float g_eo[(size_t)NSLOT * Hdim];
__device__ int   g_slot_token[NSLOT];
__device__ float g_slot_weight[NSLOT];
__device__ int   g_expert_off[10];
__device__ int   g_tok_slot[NT * 2];
__device__ int   g_tok_eidx[NT * 2];
__device__ float g_tok_w[NT * 2];

// ---------------- helpers ------------------------------------------------------
__device__ __forceinline__ uint32_t smem_u32(const void* p) {
  uint32_t r;
  asm("{ .reg .u64 t; cvta.to.shared.u64 t, %1; cvt.u32.u64 %0, t; }" : "=r"(r) : "l"(p));
  return r;
}
__device__ __forceinline__ void cp16(uint32_t s, const void* g) {
  asm volatile("cp.async.cg.shared.global [%0], [%1], 16;" :: "r"(s), "l"(g));
}
#define CP_COMMIT() asm volatile("cp.async.commit_group;" ::: "memory")
#define CP_WAIT(n)  asm volatile("cp.async.wait_group %0;" :: "n"(n) : "memory")

__device__ __forceinline__ uint32_t tf32cvt(float f) {
  uint32_t u;
  asm("cvt.rna.tf32.f32 %0, %1;" : "=r"(u) : "f"(f));
  return u;
}
__device__ __forceinline__ void mma8(float* c, const uint32_t* a, uint32_t b0, uint32_t b1) {
  asm volatile(
      "mma.sync.aligned.m16n8k8.row.col.f32.tf32.tf32.f32 "
      "{%0,%1,%2,%3},{%4,%5,%6,%7},{%8,%9},{%0,%1,%2,%3};"
      : "+f"(c[0]), "+f"(c[1]), "+f"(c[2]), "+f"(c[3])
      : "r"(a[0]), "r"(a[1]), "r"(a[2]), "r"(a[3]), "r"(b0), "r"(b1));
}

// ---------------- gating -------------------------------------------------------
__global__ __launch_bounds__(256) void gate_kernel(
    const float* __restrict__ x, const float* __restrict__ gate_w,
    const float* __restrict__ gbias) {
  int warp = threadIdx.x >> 5, lane = threadIdx.x & 31;
  int t = blockIdx.x * 8 + warp;
  if (t >= NT) return;
  const float* xr = x + (size_t)t * Hdim;
  float s[NE] = {0.f,0.f,0.f,0.f,0.f,0.f,0.f,0.f};
  for (int k = lane; k < Hdim; k += 32) {
    float xv = xr[k];
    const float* gw = gate_w + k * NE;
#pragma unroll
    for (int e = 0; e < NE; e++) s[e] += xv * gw[e];
  }
#pragma unroll
  for (int e = 0; e < NE; e++)
#pragma unroll
    for (int o = 16; o > 0; o >>= 1) s[e] += __shfl_xor_sync(0xffffffffu, s[e], o);
  if (lane == 0) {
    float sc[NE];
#pragma unroll
    for (int e = 0; e < NE; e++) sc[e] = 1.0f / (1.0f + expf(-(s[e] + gbias[e])));
    int i0 = 0;
#pragma unroll
    for (int e = 1; e < NE; e++) if (sc[e] > sc[i0]) i0 = e;
    int i1 = (i0 == 0) ? 1 : 0;
#pragma unroll
    for (int e = 0; e < NE; e++) if (e != i0 && sc[e] > sc[i1]) i1 = e;
    float denom = sc[i0] + sc[i1] + 1e-6f;
    g_tok_eidx[t*2+0] = i0;  g_tok_eidx[t*2+1] = i1;
    g_tok_w[t*2+0] = sc[i0] / denom;  g_tok_w[t*2+1] = sc[i1] / denom;
  }
}

// ---------------- routing ------------------------------------------------------
__global__ __launch_bounds__(256) void route_kernel() {
  __shared__ int counts[NE];
  __shared__ int offs[NE + 1];
  int wid = threadIdx.x >> 5, lane = threadIdx.x & 31;
  if (wid < NE) {
    int cnt = 0;
    for (int t0 = 0; t0 < NT; t0 += 32) {
      int t = t0 + lane;
      bool m = (g_tok_eidx[t*2] == wid) || (g_tok_eidx[t*2+1] == wid);
      cnt += __popc(__ballot_sync(0xffffffffu, m));
    }
    if (lane == 0) counts[wid] = cnt;
  }
  __syncthreads();
  if (threadIdx.x == 0) {
    int o = 0;
    for (int e = 0; e < NE; e++) { offs[e] = o; g_expert_off[e] = o; o += counts[e]; }
    offs[NE] = o;
    g_expert_off[NE] = SHOFF;
    g_expert_off[NE + 1] = SHOFF + NT;
  }
  __syncthreads();
  if (wid < NE) {
    int pos = offs[wid];
    for (int t0 = 0; t0 < NT; t0 += 32) {
      int t = t0 + lane;
      int e0 = g_tok_eidx[t*2], e1 = g_tok_eidx[t*2+1];
      int k = (e0 == wid) ? 0 : ((e1 == wid) ? 1 : -1);
      unsigned mask = __ballot_sync(0xffffffffu, k >= 0);
      if (k >= 0) {
        int slot = pos + __popc(mask & ((1u << lane) - 1u));
        g_slot_token[slot] = t;
        g_slot_weight[slot] = g_tok_w[t*2+k];
        g_tok_slot[t*2+k] = slot;
      }
      pos += __popc(mask);
    }
  }
  for (int t = threadIdx.x; t < NT; t += blockDim.x) {
    g_slot_token[SHOFF + t] = t;
    g_slot_weight[SHOFF + t] = 1.0f;
  }
}

// ---------------- tf32 mma.sync grouped GEMM (fragment-order smem) -------------
// 128x128 CTA tile, BK=32, 256 threads, 8 warps (4 M x 2 N), warp tile 32x64.
// raw (cp.async targets):  A[128][36] @0 (4608 f), B[32][136] @4608 (4352 f)
// fragment-order (tf32-converted, swizzled): Af @8960 (4096 f), Bf @13056 (4096 f)
// Total 17152 floats = 68608 B. 2 CTAs/SM.
#define RAWA 0
#define RAWB 4608
#define AFRG 8960
#define BFRG 13056
#define SMEM_DYN 68608

// fragment lane permutation: f(g,cq) = ((g+2cq)&7) | (cq<<3)
// physical uint4 slot: block*32 + (f ^ (block&7))

template <int KDIM, int NDIM, bool GATHER, bool IS_UP>
__global__ __launch_bounds__(256, 2)
void moe_gemm(const float* __restrict__ Abase,
              const float* __restrict__ Wexp, const float* __restrict__ Bexp,
              const float* __restrict__ Wsh,  const float* __restrict__ Bsh) {
  extern __shared__ float sm[];
  int e = blockIdx.z;
  int start = g_expert_off[e];
  int count = g_expert_off[e + 1] - start;
  int m0 = blockIdx.y * 128;
  if (m0 >= count) return;
  int n0 = blockIdx.x * 128;

  const float* Bmat = (e < NE) ? (Wexp + (size_t)e * KDIM * NDIM) : Wsh;
  const float* bias = (e < NE) ? (Bexp + (size_t)e * NDIM) : Bsh;

  const int tid  = threadIdx.x;
  const int lane = tid & 31;
  const int wid  = tid >> 5;
  const int warpM = wid & 3;
  const int warpN = wid >> 2;
  const int g  = lane >> 2;
  const int cq = lane & 3;
  const int fl = ((g + 2 * cq) & 7) | (cq << 3);   // consumer fragment slot

  // A loader: 2 threads per row, each 4 float4
  const int arow = tid >> 1;
  const int ahalf = tid & 1;
  int gmr = m0 + arow;
  int aidx = start + ((gmr < count) ? gmr : 0);
  const float* aptr;
  if (GATHER) aptr = Abase + (size_t)g_slot_token[aidx] * KDIM;
  else        aptr = g_hact + (size_t)aidx * KDIM;
  aptr += ahalf * 16;

  const uint32_t smb = smem_u32(sm);
  const uint32_t aDst = smb + arow * 144u + ahalf * 64u;       // raw A
  const uint32_t bDst = smb + RAWB * 4u;                       // raw B base

  // B loader constants (c4 = tid&31 is the same for all 4 sub-loads)
  const int bc4 = tid & 31;
  const int bwn = bc4 >> 4;
  const int bnt = (bc4 >> 1) & 7;
  const int bntp = bnt >> 1, bntl = bnt & 1;
  const int bgb = (bc4 & 1) * 4;

  // A repack constants
  const int am  = arow >> 5;
  const int amt = (arow >> 4) & 1;
  const int aga = arow & 7;
  const int arhi = (arow >> 3) & 1;
  const int axA = (2 * am + amt) & 7;          // bA&7 (ks*8 drops out mod 8)
  int fA[4];
#pragma unroll
  for (int c = 0; c < 4; c++) fA[c] = (((aga + 2 * c) & 7) | (c << 3)) ^ axA;

  uint32_t* Af = (uint32_t*)(sm + AFRG);
  uint32_t* Bf = (uint32_t*)(sm + BFRG);

  float acc[2][8][4];
#pragma unroll
  for (int mt = 0; mt < 2; mt++)
#pragma unroll
    for (int nt = 0; nt < 8; nt++)
#pragma unroll
      for (int q = 0; q < 4; q++) acc[mt][nt][q] = 0.0f;

  auto load_stage = [&](int kb) {
    const float* ap = aptr + kb;
#pragma unroll
    for (int i = 0; i < 4; i++) cp16(aDst + i * 16u, ap + i * 4);
#pragma unroll
    for (int i = 0; i < 4; i++) {
      int kr = (tid >> 5) + 8 * i;
      cp16(bDst + kr * 544u + bc4 * 16u,
           Bmat + (size_t)(kb + kr) * NDIM + n0 + bc4 * 4);
    }
    CP_COMMIT();
  };

  load_stage(0);
  const int KT = KDIM / 32;

  for (int kt = 0; kt < KT; kt++) {
    CP_WAIT(0);
    __syncthreads();                       // raw[kt] landed; frag free

    // ---- repack A: raw -> fragment order (convert once) ----
#pragma unroll
    for (int j = 0; j < 4; j++) {
      float4 v = *(const float4*)(sm + RAWA + arow * 36 + ahalf * 16 + j * 4);
      int ks = ahalf * 2 + (j >> 1);
      int comp = (j & 1) * 2 + arhi;
      int bA = 8 * ks + 2 * am + amt;
      int base = bA * 32;
      Af[(base + fA[0]) * 4 + comp] = tf32cvt(v.x);
      Af[(base + fA[1]) * 4 + comp] = tf32cvt(v.y);
      Af[(base + fA[2]) * 4 + comp] = tf32cvt(v.z);
      Af[(base + fA[3]) * 4 + comp] = tf32cvt(v.w);
    }
    // ---- repack B ----
#pragma unroll
    for (int i = 0; i < 4; i++) {
      int kr = (tid >> 5) + 8 * i;
      float4 v = *(const float4*)(sm + RAWB + kr * 136 + bc4 * 4);
      int ks = kr >> 3, cqk = kr & 3, bhi = (kr & 7) >> 2;
      int comp = bntl * 2 + bhi;
      int bB = 8 * ks + bwn * 4 + bntp;
      int xB = (bwn * 4 + bntp) & 7;
      int base = bB * 32;
      float fv[4] = {v.x, v.y, v.z, v.w};
#pragma unroll
      for (int c = 0; c < 4; c++) {
        int fb = (((bgb + c + 2 * cqk) & 7) | (cqk << 3)) ^ xB;
        Bf[(base + fb) * 4 + comp] = tf32cvt(fv[c]);
      }
    }
    __syncthreads();                       // frag ready; raw free

    if (kt + 1 < KT) load_stage((kt + 1) * 32);   // overlaps MMA below

    // ---- MMA: pure LDS.128 + HMMA ----
    const uint4* Af4 = (const uint4*)Af;
    const uint4* Bf4 = (const uint4*)Bf;
#pragma unroll
    for (int ks = 0; ks < 4; ks++) {
      int bA0 = 8 * ks + 2 * warpM;
      uint4 a0v = Af4[(bA0)     * 32 + (fl ^ (bA0 & 7))];
      uint4 a1v = Af4[(bA0 + 1) * 32 + (fl ^ ((bA0 + 1) & 7))];
      uint32_t a0[4] = {a0v.x, a0v.y, a0v.z, a0v.w};
      uint32_t a1[4] = {a1v.x, a1v.y, a1v.z, a1v.w};
#pragma unroll
      for (int ntp = 0; ntp < 4; ntp++) {
        int bB = 8 * ks + warpN * 4 + ntp;
        uint4 b = Bf4[bB * 32 + (fl ^ (bB & 7))];
        mma8(acc[0][2 * ntp],     a0, b.x, b.y);
        mma8(acc[0][2 * ntp + 1], a0, b.z, b.w);
        mma8(acc[1][2 * ntp],     a1, b.x, b.y);
        mma8(acc[1][2 * ntp + 1], a1, b.z, b.w);
      }
    }
  }

  // ---- epilogue ----
#pragma unroll
  for (int mt = 0; mt < 2; mt++) {
#pragma unroll
    for (int half = 0; half < 2; half++) {
      int r = m0 + warpM * 32 + mt * 16 + g + half * 8;
      if (r >= count) continue;
      int slot = start + r;
      float wscale = IS_UP ? 0.0f : (0.1f * g_slot_weight[slot]);
      float* dstRow = IS_UP ? (g_hact + (size_t)slot * Idim)
                            : (g_eo   + (size_t)slot * Hdim);
#pragma unroll
      for (int nt = 0; nt < 8; nt++) {
        int col = n0 + warpN * 64 + nt * 8 + cq * 2;
        float v0 = acc[mt][nt][half * 2 + 0] + __ldg(bias + col);
        float v1 = acc[mt][nt][half * 2 + 1] + __ldg(bias + col + 1);
        if (IS_UP) {
          v0 = 0.5f * v0 * (1.0f + erff(v0 * 0.70710678118654752440f));
          v1 = 0.5f * v1 * (1.0f + erff(v1 * 0.70710678118654752440f));
        } else {
          v0 *= wscale;
          v1 *= wscale;
        }
        *(float2*)(dstRow + col) = make_float2(v0, v1);
      }
    }
  }
}

// ---------------- combine ------------------------------------------------------
__global__ __launch_bounds__(256) void combine_kernel(float* __restrict__ out) {
  int t = blockIdx.x;
  int s0 = g_tok_slot[t*2+0], s1 = g_tok_slot[t*2+1];
  const float* r0 = g_eo + (size_t)(SHOFF + t) * Hdim;
  const float* ra = g_eo + (size_t)s0 * Hdim;
  const float* rb = g_eo + (size_t)s1 * Hdim;
  float v[4], mx = 0.0f;
#pragma unroll
  for (int i = 0; i < 4; i++) {
    int h = threadIdx.x + i * 256;
    float val = r0[h] + ra[h] + rb[h];
    v[i] = val;
    mx = fmaxf(mx, fabsf(val));
  }
#pragma unroll
  for (int o = 16; o > 0; o >>= 1) mx = fmaxf(mx, __shfl_xor_sync(0xffffffffu, mx, o));
  __shared__ float smax[8];
  __shared__ float bmax;
  if ((threadIdx.x & 31) == 0) smax[threadIdx.x >> 5] = mx;
  __syncthreads();
  if (threadIdx.x == 0) {
    float m = smax[0];
#pragma unroll
    for (int w = 1; w < 8; w++) m = fmaxf(m, smax[w]);
    bmax = m;
  }
  __syncthreads();
  float inv = 1.0f / (bmax + 1e-6f);
  float* op = out + (size_t)t * Hdim;
#pragma unroll
  for (int i = 0; i < 4; i++) op[threadIdx.x + i * 256] = v[i] * inv;
}

// ---------------- launch -------------------------------------------------------
extern "C" void kernel_launch(void* const* d_in, const int* in_sizes, int n_in,
                              void* d_out, int out_size) {
  const float* x       = (const float*)d_in[0];
  const float* gate_w  = (const float*)d_in[1];
  const float* bias    = (const float*)d_in[2];
  const float* up_w    = (const float*)d_in[3];
  const float* up_b    = (const float*)d_in[4];
  const float* down_w  = (const float*)d_in[5];
  const float* down_b  = (const float*)d_in[6];
  const float* sw_up   = (const float*)d_in[7];
  const float* sb_up   = (const float*)d_in[8];
  const float* sw_down = (const float*)d_in[9];
  const float* sb_down = (const float*)d_in[10];
  float* out = (float*)d_out;

  cudaFuncSetAttribute(moe_gemm<Hdim, Idim, true, true>,
                       cudaFuncAttributeMaxDynamicSharedMemorySize, SMEM_DYN);
  cudaFuncSetAttribute(moe_gemm<Idim, Hdim, false, false>,
                       cudaFuncAttributeMaxDynamicSharedMemorySize, SMEM_DYN);

  gate_kernel<<<NT / 8, 256>>>(x, gate_w, bias);
  route_kernel<<<1, 256>>>();

  dim3 gUp(Idim / 128, NT / 128, 9);
  moe_gemm<Hdim, Idim, true, true><<<gUp, 256, SMEM_DYN>>>(x, up_w, up_b, sw_up, sb_up);

  dim3 gDn(Hdim / 128, NT / 128, 9);
  moe_gemm<Idim, Hdim, false, false><<<gDn, 256, SMEM_DYN>>>(nullptr, down_w, down_b, sw_down, sb_down);

  combine_kernel<<<NT, 256>>>(out);
}

// round 11
// speedup vs baseline: 1.0337x; 1.0337x over previous
#include <cuda_runtime.h>
#include <cuda_bf16.h>
#include <math.h>
#include <stdint.h>

// Problem constants
#define Hdim 1024
#define Idim 4096
#define NE   8
#define NT   2048
#define NSLOT 6144
#define SHOFF 4096

// ---------------- scratch ------------------------------------------------------
__device__ float g_hact[(size_t)NSLOT * Idim];     // tf32-rounded up outputs
__device__ float g_eo[(size_t)NSLOT * Hdim];
__device__ float g_upw_c[(size_t)9 * Hdim * Idim]; // 9 experts (8 + shared), tf32-rounded
__device__ float g_dnw_c[(size_t)9 * Idim * Hdim];
__device__ float g_x_c[(size_t)NT * Hdim];         // tf32-rounded x
__device__ int   g_slot_token[NSLOT];
__device__ float g_slot_weight[NSLOT];
__device__ int   g_expert_off[10];
__device__ int   g_tok_slot[NT * 2];
__device__ int   g_tok_eidx[NT * 2];
__device__ float g_tok_w[NT * 2];

// ---------------- helpers ------------------------------------------------------
__device__ __forceinline__ uint32_t smem_u32(const void* p) {
  uint32_t r;
  asm("{ .reg .u64 t; cvta.to.shared.u64 t, %1; cvt.u32.u64 %0, t; }" : "=r"(r) : "l"(p));
  return r;
}
__device__ __forceinline__ void cp16(uint32_t s, const void* g) {
  asm volatile("cp.async.cg.shared.global [%0], [%1], 16;" :: "r"(s), "l"(g));
}
#define CP_COMMIT() asm volatile("cp.async.commit_group;" ::: "memory")
#define CP_WAIT(n)  asm volatile("cp.async.wait_group %0;" :: "n"(n) : "memory")

__device__ __forceinline__ uint32_t tf32cvt(float f) {
  uint32_t u;
  asm("cvt.rna.tf32.f32 %0, %1;" : "=r"(u) : "f"(f));
  return u;
}
__device__ __forceinline__ void mma8(float* c, const uint32_t* a, uint32_t b0, uint32_t b1) {
  asm volatile(
      "mma.sync.aligned.m16n8k8.row.col.f32.tf32.tf32.f32 "
      "{%0,%1,%2,%3},{%4,%5,%6,%7},{%8,%9},{%0,%1,%2,%3};"
      : "+f"(c[0]), "+f"(c[1]), "+f"(c[2]), "+f"(c[3])
      : "r"(a[0]), "r"(a[1]), "r"(a[2]), "r"(a[3]), "r"(b0), "r"(b1));
}

// ---------------- tf32 pre-conversion ------------------------------------------
__global__ __launch_bounds__(256) void conv_tf32(const float* __restrict__ src,
                                                 int which, size_t off, int n) {
  float* dst = (which == 0) ? g_upw_c : (which == 1) ? g_dnw_c : g_x_c;
  dst += off;
  int n4 = n >> 2;
  for (int i = blockIdx.x * blockDim.x + threadIdx.x; i < n4;
       i += gridDim.x * blockDim.x) {
    float4 v = ((const float4*)src)[i];
    uint4 o;
    o.x = tf32cvt(v.x);  o.y = tf32cvt(v.y);
    o.z = tf32cvt(v.z);  o.w = tf32cvt(v.w);
    ((uint4*)dst)[i] = o;
  }
}

// ---------------- gating -------------------------------------------------------
__global__ __launch_bounds__(256) void gate_kernel(
    const float* __restrict__ x, const float* __restrict__ gate_w,
    const float* __restrict__ gbias) {
  int warp = threadIdx.x >> 5, lane = threadIdx.x & 31;
  int t = blockIdx.x * 8 + warp;
  if (t >= NT) return;
  const float* xr = x + (size_t)t * Hdim;
  float s[NE] = {0.f,0.f,0.f,0.f,0.f,0.f,0.f,0.f};
  for (int k = lane; k < Hdim; k += 32) {
    float xv = xr[k];
    const float* gw = gate_w + k * NE;
#pragma unroll
    for (int e = 0; e < NE; e++) s[e] += xv * gw[e];
  }
#pragma unroll
  for (int e = 0; e < NE; e++)
#pragma unroll
    for (int o = 16; o > 0; o >>= 1) s[e] += __shfl_xor_sync(0xffffffffu, s[e], o);
  if (lane == 0) {
    float sc[NE];
#pragma unroll
    for (int e = 0; e < NE; e++) sc[e] = 1.0f / (1.0f + expf(-(s[e] + gbias[e])));
    int i0 = 0;
#pragma unroll
    for (int e = 1; e < NE; e++) if (sc[e] > sc[i0]) i0 = e;
    int i1 = (i0 == 0) ? 1 : 0;
#pragma unroll
    for (int e = 0; e < NE; e++) if (e != i0 && sc[e] > sc[i1]) i1 = e;
    float denom = sc[i0] + sc[i1] + 1e-6f;
    g_tok_eidx[t*2+0] = i0;  g_tok_eidx[t*2+1] = i1;
    g_tok_w[t*2+0] = sc[i0] / denom;  g_tok_w[t*2+1] = sc[i1] / denom;
  }
}

// ---------------- routing ------------------------------------------------------
__global__ __launch_bounds__(256) void route_kernel() {
  __shared__ int counts[NE];
  __shared__ int offs[NE + 1];
  int wid = threadIdx.x >> 5, lane = threadIdx.x & 31;
  if (wid < NE) {
    int cnt = 0;
    for (int t0 = 0; t0 < NT; t0 += 32) {
      int t = t0 + lane;
      bool m = (g_tok_eidx[t*2] == wid) || (g_tok_eidx[t*2+1] == wid);
      cnt += __popc(__ballot_sync(0xffffffffu, m));
    }
    if (lane == 0) counts[wid] = cnt;
  }
  __syncthreads();
  if (threadIdx.x == 0) {
    int o = 0;
    for (int e = 0; e < NE; e++) { offs[e] = o; g_expert_off[e] = o; o += counts[e]; }
    offs[NE] = o;
    g_expert_off[NE] = SHOFF;
    g_expert_off[NE + 1] = SHOFF + NT;
  }
  __syncthreads();
  if (wid < NE) {
    int pos = offs[wid];
    for (int t0 = 0; t0 < NT; t0 += 32) {
      int t = t0 + lane;
      int e0 = g_tok_eidx[t*2], e1 = g_tok_eidx[t*2+1];
      int k = (e0 == wid) ? 0 : ((e1 == wid) ? 1 : -1);
      unsigned mask = __ballot_sync(0xffffffffu, k >= 0);
      if (k >= 0) {
        int slot = pos + __popc(mask & ((1u << lane) - 1u));
        g_slot_token[slot] = t;
        g_slot_weight[slot] = g_tok_w[t*2+k];
        g_tok_slot[t*2+k] = slot;
      }
      pos += __popc(mask);
    }
  }
  for (int t = threadIdx.x; t < NT; t += blockDim.x) {
    g_slot_token[SHOFF + t] = t;
    g_slot_weight[SHOFF + t] = 1.0f;
  }
}

// ---------------- tf32 mma.sync grouped GEMM (pre-converted operands) ----------
// 128x128 CTA tile, BK=32, 256 threads, 8 warps (4 M x 2 N), warp tile 32x64.
// smem floats: A[2][128][36] @0 (stage stride 4608), B[2][32][136] @9216
// (stage stride 4352). Total 71680 B; 2 CTAs/SM.
#define SMEM_DYN 71680

template <int KDIM, int NDIM, bool GATHER, bool IS_UP>
__global__ __launch_bounds__(256, 2)
void moe_gemm(const float* __restrict__ Bexp, const float* __restrict__ Bsh) {
  extern __shared__ float sm[];
  int e = blockIdx.z;
  int start = g_expert_off[e];
  int count = g_expert_off[e + 1] - start;
  int m0 = blockIdx.y * 128;
  if (m0 >= count) return;
  int n0 = blockIdx.x * 128;

  const float* Bmat = (IS_UP ? g_upw_c : g_dnw_c) + (size_t)e * KDIM * NDIM;
  const float* bias = (e < NE) ? (Bexp + (size_t)e * NDIM) : Bsh;

  const int tid  = threadIdx.x;
  const int lane = tid & 31;
  const int wid  = tid >> 5;
  const int warpM = wid & 3;
  const int warpN = wid >> 2;
  const int g  = lane >> 2;
  const int cq = lane & 3;

  // A loader: 2 threads per row, each 4 float4
  const int arow = tid >> 1;
  const int ahalf = tid & 1;
  int gmr = m0 + arow;
  int aidx = start + ((gmr < count) ? gmr : 0);
  const float* aptr;
  if (GATHER) aptr = g_x_c + (size_t)g_slot_token[aidx] * KDIM;
  else        aptr = g_hact + (size_t)aidx * KDIM;
  aptr += ahalf * 16;

  const uint32_t smb = smem_u32(sm);
  const uint32_t aDst = smb + arow * 144u + ahalf * 64u;

  float acc[2][8][4];
#pragma unroll
  for (int mt = 0; mt < 2; mt++)
#pragma unroll
    for (int nt = 0; nt < 8; nt++)
#pragma unroll
      for (int q = 0; q < 4; q++) acc[mt][nt][q] = 0.0f;

  const int KT = KDIM / 32;

  auto load_stage = [&](int s, int kb) {
    uint32_t ab = aDst + (uint32_t)s * 18432u;
    const float* ap = aptr + kb;
#pragma unroll
    for (int i = 0; i < 4; i++) cp16(ab + i * 16u, ap + i * 4);
    uint32_t bb = smb + 36864u + (uint32_t)s * 17408u;
#pragma unroll
    for (int i = 0; i < 4; i++) {
      int idx = tid + 256 * i;
      int kr = idx >> 5, c4 = idx & 31;
      cp16(bb + kr * 544u + c4 * 16u,
           Bmat + (size_t)(kb + kr) * NDIM + n0 + c4 * 4);
    }
    CP_COMMIT();
  };

  load_stage(0, 0);

  for (int kt = 0; kt < KT; kt++) {
    if (kt + 1 < KT) { load_stage((kt + 1) & 1, (kt + 1) * 32); CP_WAIT(1); }
    else             { CP_WAIT(0); }
    __syncthreads();

    const uint32_t* As = (const uint32_t*)(sm + (kt & 1) * 4608);
    const uint32_t* Bs = (const uint32_t*)(sm + 9216 + (kt & 1) * 4352);
#pragma unroll
    for (int ks = 0; ks < 4; ks++) {
      int kb = ks * 8;
      uint32_t a[2][4];
#pragma unroll
      for (int mt = 0; mt < 2; mt++) {
        int r = warpM * 32 + mt * 16;
        a[mt][0] = As[(r + g)     * 36 + kb + cq];
        a[mt][1] = As[(r + 8 + g) * 36 + kb + cq];
        a[mt][2] = As[(r + g)     * 36 + kb + cq + 4];
        a[mt][3] = As[(r + 8 + g) * 36 + kb + cq + 4];
      }
#pragma unroll
      for (int nt = 0; nt < 8; nt++) {
        int nc = warpN * 64 + nt * 8;
        uint32_t b0 = Bs[(kb + cq)     * 136 + nc + g];
        uint32_t b1 = Bs[(kb + cq + 4) * 136 + nc + g];
        mma8(acc[0][nt], a[0], b0, b1);
        mma8(acc[1][nt], a[1], b0, b1);
      }
    }
    __syncthreads();
  }

  // ---- epilogue ----
#pragma unroll
  for (int mt = 0; mt < 2; mt++) {
#pragma unroll
    for (int half = 0; half < 2; half++) {
      int r = m0 + warpM * 32 + mt * 16 + g + half * 8;
      if (r >= count) continue;
      int slot = start + r;
      float wscale = IS_UP ? 0.0f : (0.1f * g_slot_weight[slot]);
      float* dstRow = IS_UP ? (g_hact + (size_t)slot * Idim)
                            : (g_eo   + (size_t)slot * Hdim);
#pragma unroll
      for (int nt = 0; nt < 8; nt++) {
        int col = n0 + warpN * 64 + nt * 8 + cq * 2;
        float v0 = acc[mt][nt][half * 2 + 0] + __ldg(bias + col);
        float v1 = acc[mt][nt][half * 2 + 1] + __ldg(bias + col + 1);
        if (IS_UP) {
          v0 = 0.5f * v0 * (1.0f + erff(v0 * 0.70710678118654752440f));
          v1 = 0.5f * v1 * (1.0f + erff(v1 * 0.70710678118654752440f));
          // store tf32-rounded so the down pass needs no conversion
          *(float2*)(dstRow + col) = make_float2(
              __uint_as_float(tf32cvt(v0)), __uint_as_float(tf32cvt(v1)));
        } else {
          v0 *= wscale;
          v1 *= wscale;
          *(float2*)(dstRow + col) = make_float2(v0, v1);
        }
      }
    }
  }
}

// ---------------- combine ------------------------------------------------------
__global__ __launch_bounds__(256) void combine_kernel(float* __restrict__ out) {
  int t = blockIdx.x;
  int s0 = g_tok_slot[t*2+0], s1 = g_tok_slot[t*2+1];
  const float* r0 = g_eo + (size_t)(SHOFF + t) * Hdim;
  const float* ra = g_eo + (size_t)s0 * Hdim;
  const float* rb = g_eo + (size_t)s1 * Hdim;
  float v[4], mx = 0.0f;
#pragma unroll
  for (int i = 0; i < 4; i++) {
    int h = threadIdx.x + i * 256;
    float val = r0[h] + ra[h] + rb[h];
    v[i] = val;
    mx = fmaxf(mx, fabsf(val));
  }
#pragma unroll
  for (int o = 16; o > 0; o >>= 1) mx = fmaxf(mx, __shfl_xor_sync(0xffffffffu, mx, o));
  __shared__ float smax[8];
  __shared__ float bmax;
  if ((threadIdx.x & 31) == 0) smax[threadIdx.x >> 5] = mx;
  __syncthreads();
  if (threadIdx.x == 0) {
    float m = smax[0];
#pragma unroll
    for (int w = 1; w < 8; w++) m = fmaxf(m, smax[w]);
    bmax = m;
  }
  __syncthreads();
  float inv = 1.0f / (bmax + 1e-6f);
  float* op = out + (size_t)t * Hdim;
#pragma unroll
  for (int i = 0; i < 4; i++) op[threadIdx.x + i * 256] = v[i] * inv;
}

// ---------------- launch -------------------------------------------------------
extern "C" void kernel_launch(void* const* d_in, const int* in_sizes, int n_in,
                              void* d_out, int out_size) {
  const float* x       = (const float*)d_in[0];
  const float* gate_w  = (const float*)d_in[1];
  const float* bias    = (const float*)d_in[2];
  const float* up_w    = (const float*)d_in[3];
  const float* up_b    = (const float*)d_in[4];
  const float* down_w  = (const float*)d_in[5];
  const float* down_b  = (const float*)d_in[6];
  const float* sw_up   = (const float*)d_in[7];
  const float* sb_up   = (const float*)d_in[8];
  const float* sw_down = (const float*)d_in[9];
  const float* sb_down = (const float*)d_in[10];
  float* out = (float*)d_out;

  cudaFuncSetAttribute(moe_gemm<Hdim, Idim, true, true>,
                       cudaFuncAttributeMaxDynamicSharedMemorySize, SMEM_DYN);
  cudaFuncSetAttribute(moe_gemm<Idim, Hdim, false, false>,
                       cudaFuncAttributeMaxDynamicSharedMemorySize, SMEM_DYN);

  // pre-convert operands to RNA-rounded tf32 bit patterns
  conv_tf32<<<2048, 256>>>(up_w,    0, 0,                      NE * Hdim * Idim);
  conv_tf32<<<2048, 256>>>(sw_up,   0, (size_t)NE * Hdim * Idim,    Hdim * Idim);
  conv_tf32<<<2048, 256>>>(down_w,  1, 0,                      NE * Idim * Hdim);
  conv_tf32<<<2048, 256>>>(sw_down, 1, (size_t)NE * Idim * Hdim,    Idim * Hdim);
  conv_tf32<<<256, 256>>>(x,        2, 0,                      NT * Hdim);

  gate_kernel<<<NT / 8, 256>>>(x, gate_w, bias);
  route_kernel<<<1, 256>>>();

  dim3 gUp(Idim / 128, NT / 128, 9);
  moe_gemm<Hdim, Idim, true, true><<<gUp, 256, SMEM_DYN>>>(up_b, sb_up);

  dim3 gDn(Hdim / 128, NT / 128, 9);
  moe_gemm<Idim, Hdim, false, false><<<gDn, 256, SMEM_DYN>>>(down_b, sb_down);

  combine_kernel<<<NT, 256>>>(out);
}